// round 8
// baseline (speedup 1.0000x reference)
#include <cuda_runtime.h>
#include <cstdint>

// SpikeFP32ScaleBy2K — streaming bit-circuit kernel, 256-bit memory ops (sm_100a).
//   out = (k == ±0) ? x : x with exponent field := (e_x + kf) & 0xFF
//   kf = s_k ? -|k| : |k|,  |k| = (0x80 | top7(m_k)) >> (7 - ((e_k-127)&7))
// Bits stored big-endian as 0.0/1.0 floats, 32 per row.
//
// R8: each lane owns 8 floats (32B) via LDG.E.256/STG.E.256 -> 4 lanes per
// row, 2-level shfl_xor butterfly, half the memory instructions vs R6.

__device__ __forceinline__ void ldg256_nc(const float* p,
    unsigned& u0, unsigned& u1, unsigned& u2, unsigned& u3,
    unsigned& u4, unsigned& u5, unsigned& u6, unsigned& u7)
{
    float f0, f1, f2, f3, f4, f5, f6, f7;
    asm volatile("ld.global.nc.v8.f32 {%0,%1,%2,%3,%4,%5,%6,%7}, [%8];"
        : "=f"(f0), "=f"(f1), "=f"(f2), "=f"(f3),
          "=f"(f4), "=f"(f5), "=f"(f6), "=f"(f7)
        : "l"(p));
    u0 = __float_as_uint(f0); u1 = __float_as_uint(f1);
    u2 = __float_as_uint(f2); u3 = __float_as_uint(f3);
    u4 = __float_as_uint(f4); u5 = __float_as_uint(f5);
    u6 = __float_as_uint(f6); u7 = __float_as_uint(f7);
}

__device__ __forceinline__ void stg256_cs(float* p,
    float f0, float f1, float f2, float f3,
    float f4, float f5, float f6, float f7)
{
    asm volatile("st.global.cs.v8.f32 [%0], {%1,%2,%3,%4,%5,%6,%7,%8};"
        :: "l"(p), "f"(f0), "f"(f1), "f"(f2), "f"(f3),
           "f"(f4), "f"(f5), "f"(f6), "f"(f7)
        : "memory");
}

__global__ __launch_bounds__(256) void spike_scale_kernel(
    const float* __restrict__ x,
    const float* __restrict__ k,
    float* __restrict__ out)
{
    long long t = (long long)blockIdx.x * blockDim.x + threadIdx.x;
    const float* xp = x + t * 8;
    const float* kp = k + t * 8;

    // This lane's byte position within the 32-bit row word (BE bit order):
    // lane group of 4; lane g owns bits [8g, 8g+8) BE -> shift 24-8g.
    const unsigned sh = 24u - 8u * ((unsigned)t & 3u);

    unsigned a0,a1,a2,a3,a4,a5,a6,a7;
    unsigned b0,b1,b2,b3,b4,b5,b6,b7;
    ldg256_nc(xp, a0,a1,a2,a3,a4,a5,a6,a7);
    ldg256_nc(kp, b0,b1,b2,b3,b4,b5,b6,b7);

    // Pack 8 bits via bit 23 (1.0f = 0x3F800000). Bit j (MSB-first) from word j:
    // ((u_j >> (16+j)) & (0x80 >> j)).
    unsigned xb = ((a0 >> 16) & 0x80u) | ((a1 >> 17) & 0x40u) |
                  ((a2 >> 18) & 0x20u) | ((a3 >> 19) & 0x10u) |
                  ((a4 >> 20) & 0x08u) | ((a5 >> 21) & 0x04u) |
                  ((a6 >> 22) & 0x02u) | ((a7 >> 23) & 0x01u);
    unsigned kb = ((b0 >> 16) & 0x80u) | ((b1 >> 17) & 0x40u) |
                  ((b2 >> 18) & 0x20u) | ((b3 >> 19) & 0x10u) |
                  ((b4 >> 20) & 0x08u) | ((b5 >> 21) & 0x04u) |
                  ((b6 >> 22) & 0x02u) | ((b7 >> 23) & 0x01u);
    unsigned xw = xb << sh;
    unsigned kw = kb << sh;

    // OR-butterfly across the 4 contiguous lanes of this row.
    #pragma unroll
    for (int m = 1; m <= 2; m <<= 1) {
        xw |= __shfl_xor_sync(0xFFFFFFFFu, xw, m);
        kw |= __shfl_xor_sync(0xFFFFFFFFu, kw, m);
    }
    // xw/kw: full words, sign@31 exp@30..23 mant@22..0.

    unsigned e_k   = (kw >> 23) & 0xFFu;
    unsigned s_k   = kw >> 31;
    unsigned kzero = ((kw & 0x7FFFFFFFu) == 0u);

    unsigned sh3  = (e_k - 127u) & 7u;
    unsigned val  = 0x80u | ((kw >> 16) & 0x7Fu);
    unsigned kabs = val >> (7u - sh3);
    unsigned kf   = s_k ? ((0u - kabs) & 0xFFu) : kabs;

    unsigned e_new = (((xw >> 23) & 0xFFu) + kf) & 0xFFu;
    unsigned ow    = kzero ? xw : ((xw & 0x807FFFFFu) | (e_new << 23));

    // Unpack this lane's 8 output bits.
    unsigned ob = ow >> sh;   // low 8 bits are this lane's byte, MSB-first
    float o0 = (ob & 0x80u) ? 1.0f : 0.0f;
    float o1 = (ob & 0x40u) ? 1.0f : 0.0f;
    float o2 = (ob & 0x20u) ? 1.0f : 0.0f;
    float o3 = (ob & 0x10u) ? 1.0f : 0.0f;
    float o4 = (ob & 0x08u) ? 1.0f : 0.0f;
    float o5 = (ob & 0x04u) ? 1.0f : 0.0f;
    float o6 = (ob & 0x02u) ? 1.0f : 0.0f;
    float o7 = (ob & 0x01u) ? 1.0f : 0.0f;

    stg256_cs(out + t * 8, o0, o1, o2, o3, o4, o5, o6, o7);
}

extern "C" void kernel_launch(void* const* d_in, const int* in_sizes, int n_in,
                              void* d_out, int out_size)
{
    const float* x = (const float*)d_in[0];
    const float* k = (const float*)d_in[1];
    float* o = (float*)d_out;

    int n8 = in_sizes[0] / 8;          // 2^23 threads, divisible by 256
    int threads = 256;
    int blocks  = n8 / threads;        // exact; no tail
    spike_scale_kernel<<<blocks, threads>>>(x, k, o);
}

// round 9
// speedup vs baseline: 1.0269x; 1.0269x over previous
#include <cuda_runtime.h>
#include <cstdint>

// SpikeFP32ScaleBy2K — streaming bit-circuit kernel (FINAL, roofline-frozen).
//   out = (k == ±0) ? x : x with exponent field := (e_x + kf) & 0xFF
//   kf = s_k ? -|k| : |k|,  |k| = (0x80 | top7(m_k)) >> (7 - ((e_k-127)&7))
// Bits stored big-endian as 0.0/1.0 floats, 32 per row.
//
// Layout: 8 lanes per row, one float4 (4 bits) per lane -> fully coalesced
// 16B accesses; row words assembled via 3-level shfl_xor OR-butterfly.
//
// Roofline evidence (5 structural variants, R1-R8): kernel time pinned at
// 109.2-109.9us, 6.89-6.95 TB/s (87% of HBM spec), DRAM 84-86%, with issue
// 20-35% / ALU 29-40% / L1 33-36% all slack. MLP, locality, cache hints,
// 256-bit ops, instruction count: all neutral. Traffic (768 MB) is
// irreducible. This is the DRAM-scheduler-bound ceiling; frozen.

__global__ __launch_bounds__(256) void spike_scale_kernel(
    const uint4* __restrict__ x,
    const uint4* __restrict__ k,
    uint4* __restrict__ out)
{
    int t = blockIdx.x * blockDim.x + threadIdx.x;

    const unsigned sh = 28u - 4u * ((unsigned)t & 7u);   // nibble pos (BE order)

    uint4 xu = x[t];
    uint4 ku = k[t];

    // Pack via bit 23: 1.0f (0x3F800000) has it set, 0.0f doesn't.
    unsigned xw = ( ((xu.x >> 20) & 8u) | ((xu.y >> 21) & 4u) |
                    ((xu.z >> 22) & 2u) | ((xu.w >> 23) & 1u) ) << sh;
    unsigned kw = ( ((ku.x >> 20) & 8u) | ((ku.y >> 21) & 4u) |
                    ((ku.z >> 22) & 2u) | ((ku.w >> 23) & 1u) ) << sh;

    // OR-butterfly across the 8 contiguous lanes of this row.
    #pragma unroll
    for (int m = 1; m <= 4; m <<= 1) {
        xw |= __shfl_xor_sync(0xFFFFFFFFu, xw, m);
        kw |= __shfl_xor_sync(0xFFFFFFFFu, kw, m);
    }
    // xw/kw now hold full words: sign@31, exp@30..23, mant@22..0.

    unsigned e_k   = (kw >> 23) & 0xFFu;
    unsigned s_k   = kw >> 31;
    unsigned kzero = ((kw & 0x7FFFFFFFu) == 0u);

    unsigned sh3  = (e_k - 127u) & 7u;
    unsigned val  = 0x80u | ((kw >> 16) & 0x7Fu);
    unsigned kabs = val >> (7u - sh3);
    unsigned kf   = s_k ? ((0u - kabs) & 0xFFu) : kabs;

    unsigned e_new = (((xw >> 23) & 0xFFu) + kf) & 0xFFu;
    unsigned ow    = kzero ? xw : ((xw & 0x807FFFFFu) | (e_new << 23));

    // Unpack this lane's 4 output bits; store non-temporal (never re-read).
    unsigned b = ow >> sh;
    uint4 o;
    o.x = (b & 8u) ? 0x3F800000u : 0u;
    o.y = (b & 4u) ? 0x3F800000u : 0u;
    o.z = (b & 2u) ? 0x3F800000u : 0u;
    o.w = (b & 1u) ? 0x3F800000u : 0u;
    __stcs(&out[t], o);
}

extern "C" void kernel_launch(void* const* d_in, const int* in_sizes, int n_in,
                              void* d_out, int out_size)
{
    const uint4* x = (const uint4*)d_in[0];
    const uint4* k = (const uint4*)d_in[1];
    uint4* o = (uint4*)d_out;

    int n4 = in_sizes[0] / 4;          // 2^24 float4s — divisible by 256
    int threads = 256;
    int blocks  = n4 / threads;        // exact; no tail
    spike_scale_kernel<<<blocks, threads>>>(x, k, o);
}